// round 1
// baseline (speedup 1.0000x reference)
#include <cuda_runtime.h>

#define Bc 8
#define Gc 256
#define Nc 1024
#define Pc 4
#define Fc 256
#define Kc 4

// ---------------- scratch (device globals; no allocation allowed) ----------
__device__ float g_v1[Pc * Gc];
__device__ float g_v2[Pc * Gc];
__device__ float g_c1[Pc];
__device__ float g_c2[Pc];
__device__ float g_e1[Bc * Pc * Nc];
__device__ float g_e2[Bc * Pc * Nc];
__device__ float g_aij[(size_t)Bc * Pc * Nc * Nc];      // 128 MB
__device__ float g_z[(size_t)Bc * Pc * Kc * Gc * Nc];   // 128 MB

// ---------------- tiny prep: v1/v2[p,g], c1/c2[p] ---------------------------
__global__ void prep_kernel(const float* __restrict__ mixer,
                            const float* __restrict__ weight,
                            const float* __restrict__ wb) {
    int p = blockIdx.x, g = threadIdx.x;
    float v1 = 0.f, v2 = 0.f;
#pragma unroll 8
    for (int f = 0; f < Fc; ++f) {
        float w = weight[((size_t)(p * Fc + f)) * Gc + g];
        v1 = fmaf(mixer[p * 2 * Fc + f], w, v1);
        v2 = fmaf(mixer[p * 2 * Fc + Fc + f], w, v2);
    }
    g_v1[p * Gc + g] = v1;
    g_v2[p * Gc + g] = v2;
    if (g == 0) {
        float c1 = 0.f, c2 = 0.f;
        for (int f = 0; f < Fc; ++f) {
            c1 = fmaf(mixer[p * 2 * Fc + f], wb[p * Fc + f], c1);
            c2 = fmaf(mixer[p * 2 * Fc + Fc + f], wb[p * Fc + f], c2);
        }
        g_c1[p] = c1;
        g_c2[p] = c2;
    }
}

// ---------------- e1/e2[b,p,n] = v·x + c ------------------------------------
__global__ void e_kernel(const float* __restrict__ x) {
    int bp = blockIdx.y;
    int b = bp >> 2, p = bp & 3;
    int n = blockIdx.x * blockDim.x + threadIdx.x;
    __shared__ float s1[Gc], s2[Gc];
    s1[threadIdx.x] = g_v1[p * Gc + threadIdx.x];
    s2[threadIdx.x] = g_v2[p * Gc + threadIdx.x];
    __syncthreads();
    const float* xb = x + (size_t)b * Gc * Nc + n;
    float a1 = 0.f, a2 = 0.f;
#pragma unroll 8
    for (int g = 0; g < Gc; ++g) {
        float xv = xb[(size_t)g * Nc];
        a1 = fmaf(s1[g], xv, a1);
        a2 = fmaf(s2[g], xv, a2);
    }
    g_e1[bp * Nc + n] = a1 + g_c1[p];
    g_e2[bp * Nc + n] = a2 + g_c2[p];
}

// ---------------- block reductions ------------------------------------------
__device__ __forceinline__ float blockReduceMax(float v, float* sm) {
#pragma unroll
    for (int o = 16; o; o >>= 1) v = fmaxf(v, __shfl_xor_sync(0xffffffffu, v, o));
    if ((threadIdx.x & 31) == 0) sm[threadIdx.x >> 5] = v;
    __syncthreads();
    if (threadIdx.x < 32) {
        float t = (threadIdx.x < 8) ? sm[threadIdx.x] : -3.0e38f;
#pragma unroll
        for (int o = 4; o; o >>= 1) t = fmaxf(t, __shfl_xor_sync(0xffffffffu, t, o));
        if (threadIdx.x == 0) sm[0] = t;
    }
    __syncthreads();
    float r = sm[0];
    __syncthreads();
    return r;
}

__device__ __forceinline__ float blockReduceSum(float v, float* sm) {
#pragma unroll
    for (int o = 16; o; o >>= 1) v += __shfl_xor_sync(0xffffffffu, v, o);
    if ((threadIdx.x & 31) == 0) sm[threadIdx.x >> 5] = v;
    __syncthreads();
    if (threadIdx.x < 32) {
        float t = (threadIdx.x < 8) ? sm[threadIdx.x] : 0.f;
#pragma unroll
        for (int o = 4; o; o >>= 1) t += __shfl_xor_sync(0xffffffffu, t, o);
        if (threadIdx.x == 0) sm[0] = t;
    }
    __syncthreads();
    float r = sm[0];
    __syncthreads();
    return r;
}

// ---------------- masked softmax rows: aij[b,p,i,:] --------------------------
__global__ void aij_kernel(const float* __restrict__ S) {
    int i = blockIdx.x, bp = blockIdx.y, b = bp >> 2;
    __shared__ float sm[8];
    float e2i = g_e2[bp * Nc + i];
    const float* e1r = g_e1 + bp * Nc;
    const float* Sr = S + (size_t)b * Nc * Nc + (size_t)i * Nc;
    float lv[4];
    int mk[4];
    float vmax = -3.0e38f;
#pragma unroll
    for (int q = 0; q < 4; ++q) {
        int j = threadIdx.x + q * 256;
        float s = Sr[j];
        int m = (fabsf(s) > 1e-9f);
        float e = e1r[j] + e2i;
        float l = e > 0.f ? e : 0.2f * e;   // leaky_relu slope 0.2
        lv[q] = l;
        mk[q] = m;
        if (m) vmax = fmaxf(vmax, l);
    }
    vmax = blockReduceMax(vmax, sm);
    float pv[4];
    float sum = 0.f;
#pragma unroll
    for (int q = 0; q < 4; ++q) {
        float pe = mk[q] ? __expf(lv[q] - vmax) : 0.f;
        pv[q] = pe;
        sum += pe;
    }
    sum = blockReduceSum(sum, sm);
    float inv = 1.f / sum;
    float* arow = g_aij + (size_t)bp * Nc * Nc + (size_t)i * Nc;
#pragma unroll
    for (int q = 0; q < 4; ++q) {
        int j = threadIdx.x + q * 256;
        arow[j] = pv[q] * inv;
    }
}

// ---------------- copy x into z[:, :, k=0] -----------------------------------
__global__ void copyx_kernel(const float4* __restrict__ x4) {
    int t = blockIdx.x * blockDim.x + threadIdx.x;
    const int GN4 = Gc * Nc / 4;
    int bp = t / GN4, r = t - bp * GN4;
    int b = bp >> 2;
    ((float4*)g_z)[(size_t)bp * Kc * GN4 + r] = x4[(size_t)b * GN4 + r];
}

// ---------------- batched SGEMM 256 x 1024 x 1024 ----------------------------
// mode 0: C = z[bp,k] = z[bp,k-1] @ aij[bp]
// mode 1: out[bp]    = lrelu( fw[p] @ Zmat[bp] + bias, 0.01 )
#define BM 128
#define BN 64
#define BK 16

__global__ void __launch_bounds__(256, 3)
gemm_kernel(const float* __restrict__ fw, const float* __restrict__ bias,
            float* __restrict__ out, int mode, int kstep) {
    const int bp = blockIdx.z, b = bp >> 2, p = bp & 3;
    const size_t GN = (size_t)Gc * Nc;
    const size_t NN = (size_t)Nc * Nc;
    const float* A;
    const float* Bm;
    float* C;
    if (mode == 0) {
        A = g_z + (size_t)bp * Kc * GN + (size_t)(kstep - 1) * GN;
        Bm = g_aij + (size_t)bp * NN;
        C = g_z + (size_t)bp * Kc * GN + (size_t)kstep * GN;
    } else {
        A = fw + (size_t)p * Fc * (Kc * Gc);  // fw[p]: 256 x 1024 row-major
        Bm = g_z + (size_t)bp * Kc * GN;      // 1024 x 1024 row-major
        C = out + ((size_t)b * Pc * Fc + (size_t)p * Fc) * Nc;
    }
    const int m0 = blockIdx.y * BM;
    const int n0 = blockIdx.x * BN;

    __shared__ float As[BK][BM];
    __shared__ float Bs[BK][BN];

    const int tid = threadIdx.x;
    const int tx = tid & 15;   // -> n, 4 cols
    const int ty = tid >> 4;   // -> m, 8 rows

    float acc[8][4];
#pragma unroll
    for (int i = 0; i < 8; ++i)
#pragma unroll
        for (int j = 0; j < 4; ++j) acc[i][j] = 0.f;

    for (int k0 = 0; k0 < 1024; k0 += BK) {
        // A tile 128x16 (transpose into As[k][m]); 512 float4, 2 per thread
#pragma unroll
        for (int l = 0; l < 2; ++l) {
            int f = tid + l * 256;
            int row = f >> 2, c4 = f & 3;
            float4 v = *(const float4*)(A + (size_t)(m0 + row) * Nc + k0 + c4 * 4);
            As[c4 * 4 + 0][row] = v.x;
            As[c4 * 4 + 1][row] = v.y;
            As[c4 * 4 + 2][row] = v.z;
            As[c4 * 4 + 3][row] = v.w;
        }
        // B tile 16x64; 256 float4, 1 per thread
        {
            int kr = tid >> 4, n4 = tid & 15;
            float4 v = *(const float4*)(Bm + (size_t)(k0 + kr) * Nc + n0 + n4 * 4);
            *(float4*)&Bs[kr][n4 * 4] = v;
        }
        __syncthreads();
#pragma unroll
        for (int kk = 0; kk < BK; ++kk) {
            float4 a0 = *(const float4*)&As[kk][ty * 8];
            float4 a1 = *(const float4*)&As[kk][ty * 8 + 4];
            float4 bv = *(const float4*)&Bs[kk][tx * 4];
            float av[8] = {a0.x, a0.y, a0.z, a0.w, a1.x, a1.y, a1.z, a1.w};
            float bw[4] = {bv.x, bv.y, bv.z, bv.w};
#pragma unroll
            for (int i = 0; i < 8; ++i)
#pragma unroll
                for (int j = 0; j < 4; ++j)
                    acc[i][j] = fmaf(av[i], bw[j], acc[i][j]);
        }
        __syncthreads();
    }

    if (mode == 0) {
#pragma unroll
        for (int i = 0; i < 8; ++i) {
            int m = m0 + ty * 8 + i;
            float4 v = make_float4(acc[i][0], acc[i][1], acc[i][2], acc[i][3]);
            *(float4*)(C + (size_t)m * Nc + n0 + tx * 4) = v;
        }
    } else {
#pragma unroll
        for (int i = 0; i < 8; ++i) {
            int m = m0 + ty * 8 + i;
            float bvs = bias[m];
            float4 v;
            float t;
            t = acc[i][0] + bvs; v.x = t > 0.f ? t : 0.01f * t;
            t = acc[i][1] + bvs; v.y = t > 0.f ? t : 0.01f * t;
            t = acc[i][2] + bvs; v.z = t > 0.f ? t : 0.01f * t;
            t = acc[i][3] + bvs; v.w = t > 0.f ? t : 0.01f * t;
            *(float4*)(C + (size_t)m * Nc + n0 + tx * 4) = v;
        }
    }
}

// ---------------- launch ------------------------------------------------------
extern "C" void kernel_launch(void* const* d_in, const int* in_sizes, int n_in,
                              void* d_out, int out_size) {
    const float* x      = (const float*)d_in[0];
    const float* mixer  = (const float*)d_in[1];
    const float* weight = (const float*)d_in[2];
    const float* wb     = (const float*)d_in[3];
    const float* fw     = (const float*)d_in[4];
    const float* bias   = (const float*)d_in[5];
    const float* S      = (const float*)d_in[6];
    float* out = (float*)d_out;

    prep_kernel<<<Pc, 256>>>(mixer, weight, wb);
    e_kernel<<<dim3(Nc / 256, Bc * Pc), 256>>>(x);
    aij_kernel<<<dim3(Nc, Bc * Pc), 256>>>(S);
    copyx_kernel<<<(Bc * Pc * Gc * Nc / 4) / 256, 256>>>((const float4*)x);

    dim3 gg(Nc / BN, 256 / BM, Bc * Pc);
    for (int k = 1; k < Kc; ++k)
        gemm_kernel<<<gg, 256>>>(fw, bias, out, 0, k);
    gemm_kernel<<<gg, 256>>>(fw, bias, out, 1, 0);
}

// round 3
// speedup vs baseline: 2.0563x; 2.0563x over previous
#include <cuda_runtime.h>
#include <cuda_bf16.h>
#include <cstdint>

#define Bc 8
#define Gc 256
#define Nn 1024
#define Pc 4
#define Fc 256
#define Kc 4
#define NBP 32

// ======================= device scratch ======================================
__device__ float g_v1[Pc * Gc];
__device__ float g_v2[Pc * Gc];
__device__ float g_c1[Pc];
__device__ float g_c2[Pc];
__device__ float g_e1[NBP * Nn];
__device__ float g_e2[NBP * Nn];
__device__ float g_aij[(size_t)NBP * Nn * Nn];          // 128 MB fp32
__device__ __nv_bfloat16 g_aTh[(size_t)NBP * Nn * Nn];  // 64 MB  aij^T hi
__device__ __nv_bfloat16 g_aTl[(size_t)NBP * Nn * Nn];  // 64 MB  aij^T lo
__device__ float g_zf[(size_t)NBP * Gc * Nn];           // 32 MB  current z (fp32)
__device__ __nv_bfloat16 g_zh[(size_t)NBP * Gc * Nn];   // 16 MB
__device__ __nv_bfloat16 g_zl[(size_t)NBP * Gc * Nn];   // 16 MB
__device__ __nv_bfloat16 g_ZTh[(size_t)NBP * Nn * Nn];  // 64 MB  Z^T[n][k*G+g] hi
__device__ __nv_bfloat16 g_ZTl[(size_t)NBP * Nn * Nn];  // 64 MB
__device__ __nv_bfloat16 g_xh[(size_t)Bc * Gc * Nn];    // 4 MB
__device__ __nv_bfloat16 g_xl[(size_t)Bc * Gc * Nn];
__device__ __nv_bfloat16 g_fwh[(size_t)Pc * Fc * Kc * Gc];  // 2 MB
__device__ __nv_bfloat16 g_fwl[(size_t)Pc * Fc * Kc * Gc];

__device__ __forceinline__ void split2(float v, __nv_bfloat16& h, __nv_bfloat16& l) {
    h = __float2bfloat16(v);
    l = __float2bfloat16(v - __bfloat162float(h));
}

// ======================= small helpers =======================================
__device__ __forceinline__ uint32_t smem_u32(const void* p) {
    uint32_t a;
    asm("{ .reg .u64 t; cvta.to.shared.u64 t, %1; cvt.u32.u64 %0, t; }" : "=r"(a) : "l"(p));
    return a;
}
__device__ __forceinline__ void cpa16(uint32_t dst, const void* src) {
    asm volatile("cp.async.cg.shared.global [%0], [%1], 16;" :: "r"(dst), "l"(src));
}
__device__ __forceinline__ void cpa_commit() { asm volatile("cp.async.commit_group;" ::: "memory"); }

#define SWZ(off) ((off) ^ (((off) >> 3) & 0x70))

__device__ __forceinline__ void ldm_x4(uint32_t& r0, uint32_t& r1, uint32_t& r2, uint32_t& r3,
                                       uint32_t addr) {
    asm volatile("ldmatrix.sync.aligned.m8n8.x4.shared.b16 {%0,%1,%2,%3}, [%4];"
                 : "=r"(r0), "=r"(r1), "=r"(r2), "=r"(r3) : "r"(addr));
}
__device__ __forceinline__ void mma16816(float* c, const uint32_t* a, const uint32_t* b) {
    asm volatile(
        "mma.sync.aligned.m16n8k16.row.col.f32.bf16.bf16.f32 "
        "{%0,%1,%2,%3}, {%4,%5,%6,%7}, {%8,%9}, {%0,%1,%2,%3};"
        : "+f"(c[0]), "+f"(c[1]), "+f"(c[2]), "+f"(c[3])
        : "r"(a[0]), "r"(a[1]), "r"(a[2]), "r"(a[3]), "r"(b[0]), "r"(b[1]));
}

// ======================= prep: v1/v2[p,g], c1/c2[p] ==========================
__global__ void prep_kernel(const float* __restrict__ mixer,
                            const float* __restrict__ weight,
                            const float* __restrict__ wb) {
    int p = blockIdx.x, g = threadIdx.x;
    float v1 = 0.f, v2 = 0.f;
#pragma unroll 8
    for (int f = 0; f < Fc; ++f) {
        float w = weight[((size_t)(p * Fc + f)) * Gc + g];
        v1 = fmaf(mixer[p * 2 * Fc + f], w, v1);
        v2 = fmaf(mixer[p * 2 * Fc + Fc + f], w, v2);
    }
    g_v1[p * Gc + g] = v1;
    g_v2[p * Gc + g] = v2;
    if (g == 0) {
        float c1 = 0.f, c2 = 0.f;
        for (int f = 0; f < Fc; ++f) {
            c1 = fmaf(mixer[p * 2 * Fc + f], wb[p * Fc + f], c1);
            c2 = fmaf(mixer[p * 2 * Fc + Fc + f], wb[p * Fc + f], c2);
        }
        g_c1[p] = c1;
        g_c2[p] = c2;
    }
}

// ======================= e1/e2 ================================================
__global__ void e_kernel(const float* __restrict__ x) {
    int bp = blockIdx.y;
    int b = bp >> 2, p = bp & 3;
    int n = blockIdx.x * blockDim.x + threadIdx.x;
    __shared__ float s1[Gc], s2[Gc];
    s1[threadIdx.x] = g_v1[p * Gc + threadIdx.x];
    s2[threadIdx.x] = g_v2[p * Gc + threadIdx.x];
    __syncthreads();
    const float* xb = x + (size_t)b * Gc * Nn + n;
    float a1 = 0.f, a2 = 0.f;
#pragma unroll 8
    for (int g = 0; g < Gc; ++g) {
        float xv = xb[(size_t)g * Nn];
        a1 = fmaf(s1[g], xv, a1);
        a2 = fmaf(s2[g], xv, a2);
    }
    g_e1[bp * Nn + n] = a1 + g_c1[p];
    g_e2[bp * Nn + n] = a2 + g_c2[p];
}

// ======================= reductions ==========================================
__device__ __forceinline__ float blockReduceMax(float v, float* sm) {
#pragma unroll
    for (int o = 16; o; o >>= 1) v = fmaxf(v, __shfl_xor_sync(0xffffffffu, v, o));
    if ((threadIdx.x & 31) == 0) sm[threadIdx.x >> 5] = v;
    __syncthreads();
    if (threadIdx.x < 32) {
        float t = (threadIdx.x < 8) ? sm[threadIdx.x] : -3.0e38f;
#pragma unroll
        for (int o = 4; o; o >>= 1) t = fmaxf(t, __shfl_xor_sync(0xffffffffu, t, o));
        if (threadIdx.x == 0) sm[0] = t;
    }
    __syncthreads();
    float r = sm[0];
    __syncthreads();
    return r;
}
__device__ __forceinline__ float blockReduceSum(float v, float* sm) {
#pragma unroll
    for (int o = 16; o; o >>= 1) v += __shfl_xor_sync(0xffffffffu, v, o);
    if ((threadIdx.x & 31) == 0) sm[threadIdx.x >> 5] = v;
    __syncthreads();
    if (threadIdx.x < 32) {
        float t = (threadIdx.x < 8) ? sm[threadIdx.x] : 0.f;
#pragma unroll
        for (int o = 4; o; o >>= 1) t += __shfl_xor_sync(0xffffffffu, t, o);
        if (threadIdx.x == 0) sm[0] = t;
    }
    __syncthreads();
    float r = sm[0];
    __syncthreads();
    return r;
}

// ======================= softmax rows (fp32 aij) ==============================
__global__ void aij_kernel(const float* __restrict__ S) {
    int i = blockIdx.x, bp = blockIdx.y, b = bp >> 2;
    __shared__ float sm[8];
    float e2i = g_e2[bp * Nn + i];
    const float* e1r = g_e1 + bp * Nn;
    const float* Sr = S + (size_t)b * Nn * Nn + (size_t)i * Nn;
    float lv[4];
    int mk[4];
    float vmax = -3.0e38f;
#pragma unroll
    for (int q = 0; q < 4; ++q) {
        int j = threadIdx.x + q * 256;
        float s = Sr[j];
        int m = (fabsf(s) > 1e-9f);
        float e = e1r[j] + e2i;
        float l = e > 0.f ? e : 0.2f * e;
        lv[q] = l;
        mk[q] = m;
        if (m) vmax = fmaxf(vmax, l);
    }
    vmax = blockReduceMax(vmax, sm);
    float pv[4];
    float sum = 0.f;
#pragma unroll
    for (int q = 0; q < 4; ++q) {
        float pe = mk[q] ? __expf(lv[q] - vmax) : 0.f;
        pv[q] = pe;
        sum += pe;
    }
    sum = blockReduceSum(sum, sm);
    float inv = 1.f / sum;
    float* arow = g_aij + (size_t)bp * Nn * Nn + (size_t)i * Nn;
#pragma unroll
    for (int q = 0; q < 4; ++q) {
        int j = threadIdx.x + q * 256;
        arow[j] = pv[q] * inv;
    }
}

// ======================= aij -> aij^T (bf16 hi/lo) ============================
__global__ void aT_kernel() {
    int bp = blockIdx.z;
    int i0 = blockIdx.y * 32, j0 = blockIdx.x * 32;
    __shared__ float t[32][33];
    int tx = threadIdx.x, ty = threadIdx.y;
    const float* src = g_aij + (size_t)bp * Nn * Nn;
#pragma unroll
    for (int q = 0; q < 4; ++q) {
        int i = ty + q * 8;
        t[i][tx] = src[(size_t)(i0 + i) * Nn + j0 + tx];
    }
    __syncthreads();
#pragma unroll
    for (int q = 0; q < 4; ++q) {
        int j = ty + q * 8;
        float v = t[tx][j];  // aij[i0+tx][j0+j]
        __nv_bfloat16 h, l;
        split2(v, h, l);
        size_t o = (size_t)bp * Nn * Nn + (size_t)(j0 + j) * Nn + i0 + tx;
        g_aTh[o] = h;   // aTh[n][j] = aij[j][n]
        g_aTl[o] = l;
    }
}

// ======================= x -> x_hi/lo + ZT slice k=0 ==========================
__global__ void splitx_kernel(const float* __restrict__ x) {
    int b = blockIdx.z;
    int g0 = blockIdx.y * 32, n0 = blockIdx.x * 32;
    __shared__ float t[32][33];
    int tx = threadIdx.x, ty = threadIdx.y;
    const float* xp = x + ((size_t)b * Gc + g0) * Nn + n0;
#pragma unroll
    for (int q = 0; q < 4; ++q) {
        int g = ty + q * 8;
        float v = xp[(size_t)g * Nn + tx];
        t[g][tx] = v;
        __nv_bfloat16 h, l;
        split2(v, h, l);
        size_t o = ((size_t)b * Gc + g0 + g) * Nn + n0 + tx;
        g_xh[o] = h;
        g_xl[o] = l;
    }
    __syncthreads();
#pragma unroll
    for (int q = 0; q < 4; ++q) {
        int n = ty + q * 8;
        float v = t[tx][n];  // x[b][g0+tx][n0+n]
        __nv_bfloat16 h, l;
        split2(v, h, l);
#pragma unroll
        for (int p = 0; p < 4; ++p) {
            size_t bp = (size_t)b * 4 + p;
            size_t o = (bp * Nn + n0 + n) * Nn + 0 * Gc + g0 + tx;
            g_ZTh[o] = h;
            g_ZTl[o] = l;
        }
    }
}

// ======================= z(fp32) -> ZT slice k (transpose-split) ==============
__global__ void ztrans_kernel(int kstep) {
    int bp = blockIdx.z;
    int g0 = blockIdx.y * 32, n0 = blockIdx.x * 32;
    __shared__ float t[32][33];
    int tx = threadIdx.x, ty = threadIdx.y;
    const float* zp = g_zf + ((size_t)bp * Gc + g0) * Nn + n0;
#pragma unroll
    for (int q = 0; q < 4; ++q) {
        int g = ty + q * 8;
        t[g][tx] = zp[(size_t)g * Nn + tx];
    }
    __syncthreads();
#pragma unroll
    for (int q = 0; q < 4; ++q) {
        int n = ty + q * 8;
        float v = t[tx][n];
        __nv_bfloat16 h, l;
        split2(v, h, l);
        size_t o = ((size_t)bp * Nn + n0 + n) * Nn + (size_t)kstep * Gc + g0 + tx;
        g_ZTh[o] = h;
        g_ZTl[o] = l;
    }
}

// ======================= fw -> bf16 hi/lo =====================================
__global__ void splitfw_kernel(const float* __restrict__ fw) {
    int i = blockIdx.x * blockDim.x + threadIdx.x;
    const int total = Pc * Fc * Kc * Gc;
    for (; i < total; i += gridDim.x * blockDim.x) {
        __nv_bfloat16 h, l;
        split2(fw[i], h, l);
        g_fwh[i] = h;
        g_fwl[i] = l;
    }
}

// ======================= HMMA GEMM ============================================
// C[128 x 128] per CTA, K=1024, BK=32, double-buffered cp.async.
// Smem tile layout (per stage): A region 16 KB, B region 16 KB.
//   row-major, 128 rows x 128 bytes: bytes [0,64)=hi k0..31, [64,128)=lo k0..31
//   swizzled with SWZ for conflict-free ldmatrix.
// mode 0: z_k = z_{k-1} @ aij   (A = z/x hi/lo [g][k], B = aij^T hi/lo [n][k])
// mode 1: out = lrelu(fw @ Z + bias)
#define TBK 32
#define NCH (Nn / TBK)
#define STG 32768
#define SMEM_GEMM (2 * STG)

__global__ void __launch_bounds__(256, 1)
mma_gemm(const float* __restrict__ bias, float* __restrict__ out, int mode, int kstep) {
    extern __shared__ __align__(1024) char smem[];
    uint32_t sb = smem_u32(smem);
    const int bp = blockIdx.z, b = bp >> 2, p = bp & 3;
    const int m0 = blockIdx.y * 128, n0 = blockIdx.x * 128;
    const int tid = threadIdx.x, wid = tid >> 5, lane = tid & 31;
    const int warp_m = wid >> 2, warp_n = wid & 3;  // 2 x 4 warps
    const size_t GN = (size_t)Gc * Nn;
    const size_t NN = (size_t)Nn * Nn;

    const __nv_bfloat16 *Ah, *Al, *Bh, *Bl;
    if (mode == 0) {
        if (kstep == 1) { Ah = g_xh + (size_t)b * GN;  Al = g_xl + (size_t)b * GN; }
        else            { Ah = g_zh + (size_t)bp * GN; Al = g_zl + (size_t)bp * GN; }
        Bh = g_aTh + (size_t)bp * NN;
        Bl = g_aTl + (size_t)bp * NN;
    } else {
        Ah = g_fwh + (size_t)p * Fc * Kc * Gc;
        Al = g_fwl + (size_t)p * Fc * Kc * Gc;
        Bh = g_ZTh + (size_t)bp * NN;
        Bl = g_ZTl + (size_t)bp * NN;
    }

    float acc[4][4][4];
#pragma unroll
    for (int i = 0; i < 4; ++i)
#pragma unroll
        for (int j = 0; j < 4; ++j)
#pragma unroll
            for (int q = 0; q < 4; ++q) acc[i][j][q] = 0.f;

    // precompute ldmatrix lane addresses (offsets within A/B tile region)
    // A: row = warp_m*64 + mt*16 + (lane&7) + ((lane>>3)&1)*8 ; chunk += (lane>>4)
    const int a_row = warp_m * 64 + (lane & 7) + ((lane >> 3) & 1) * 8;
    const int a_chx = (lane >> 4);  // 0/1
    // B: row = warp_n*32 + q*16 + (lane&7) + ((lane>>4)&1)*8 ; chunk += (lane>>3)&1
    const int b_row = warp_n * 32 + (lane & 7) + ((lane >> 4) & 1) * 8;
    const int b_chx = (lane >> 3) & 1;

    auto load_stage = [&](int c, int s) {
        uint32_t base = sb + s * STG;
        int k0 = c * TBK;
#pragma unroll
        for (int i = 0; i < 8; ++i) {
            int idx = i * 256 + tid;            // [0, 2048)
            int part = idx >> 10;               // 0 = A, 1 = B
            int r = (idx >> 3) & 127;
            int ch = idx & 7;                   // 0-3 hi, 4-7 lo
            const __nv_bfloat16* hp;
            const __nv_bfloat16* lp;
            int row;
            if (part == 0) { hp = Ah; lp = Al; row = m0 + r; }
            else           { hp = Bh; lp = Bl; row = n0 + r; }
            const __nv_bfloat16* src =
                ((ch < 4) ? hp : lp) + (size_t)row * Nn + k0 + (ch & 3) * 8;
            cpa16(base + part * 16384 + SWZ(r * 128 + ch * 16), src);
        }
        cpa_commit();
    };

    load_stage(0, 0);
    for (int c = 0; c < NCH; ++c) {
        if (c + 1 < NCH) {
            load_stage(c + 1, (c + 1) & 1);
            asm volatile("cp.async.wait_group 1;" ::: "memory");
        } else {
            asm volatile("cp.async.wait_group 0;" ::: "memory");
        }
        __syncthreads();
        uint32_t Abase = sb + (c & 1) * STG;
        uint32_t Bbase = Abase + 16384;
#pragma unroll
        for (int s = 0; s < 2; ++s) {   // two k16 steps per BK32
            uint32_t ah[4][4], al[4][4], bh[4][2], bl[4][2];
#pragma unroll
            for (int mt = 0; mt < 4; ++mt) {
                int row = a_row + mt * 16;
                int chh = s * 2 + a_chx;
                ldm_x4(ah[mt][0], ah[mt][1], ah[mt][2], ah[mt][3],
                       Abase + SWZ(row * 128 + chh * 16));
                ldm_x4(al[mt][0], al[mt][1], al[mt][2], al[mt][3],
                       Abase + SWZ(row * 128 + (chh + 4) * 16));
            }
#pragma unroll
            for (int q = 0; q < 2; ++q) {
                int row = b_row + q * 16;
                int chh = s * 2 + b_chx;
                ldm_x4(bh[2 * q][0], bh[2 * q][1], bh[2 * q + 1][0], bh[2 * q + 1][1],
                       Bbase + SWZ(row * 128 + chh * 16));
                ldm_x4(bl[2 * q][0], bl[2 * q][1], bl[2 * q + 1][0], bl[2 * q + 1][1],
                       Bbase + SWZ(row * 128 + (chh + 4) * 16));
            }
#pragma unroll
            for (int mt = 0; mt < 4; ++mt)
#pragma unroll
                for (int nt = 0; nt < 4; ++nt) {
                    mma16816(acc[mt][nt], ah[mt], bh[nt]);
                    mma16816(acc[mt][nt], ah[mt], bl[nt]);
                    mma16816(acc[mt][nt], al[mt], bh[nt]);
                }
        }
        __syncthreads();
    }

    // ---------------- epilogue ----------------
    if (mode == 0) {
        float* C = g_zf + (size_t)bp * GN;
        __nv_bfloat16* Zh = g_zh + (size_t)bp * GN;
        __nv_bfloat16* Zl = g_zl + (size_t)bp * GN;
#pragma unroll
        for (int mt = 0; mt < 4; ++mt)
#pragma unroll
            for (int nt = 0; nt < 4; ++nt) {
                int r0 = m0 + warp_m * 64 + mt * 16 + (lane >> 2);
                int cc = n0 + warp_n * 32 + nt * 8 + (lane & 3) * 2;
#pragma unroll
                for (int h = 0; h < 2; ++h) {
                    int r = r0 + h * 8;
                    float v0 = acc[mt][nt][2 * h], v1 = acc[mt][nt][2 * h + 1];
                    *(float2*)(C + (size_t)r * Nn + cc) = make_float2(v0, v1);
                    __nv_bfloat16 h0, l0, h1, l1;
                    split2(v0, h0, l0);
                    split2(v1, h1, l1);
                    __nv_bfloat162 ph, pl;
                    ph.x = h0; ph.y = h1;
                    pl.x = l0; pl.y = l1;
                    *(__nv_bfloat162*)(Zh + (size_t)r * Nn + cc) = ph;
                    *(__nv_bfloat162*)(Zl + (size_t)r * Nn + cc) = pl;
                }
            }
    } else {
        float* C = out + (size_t)bp * Fc * Nn;
#pragma unroll
        for (int mt = 0; mt < 4; ++mt)
#pragma unroll
            for (int nt = 0; nt < 4; ++nt) {
                int r0 = m0 + warp_m * 64 + mt * 16 + (lane >> 2);
                int cc = n0 + warp_n * 32 + nt * 8 + (lane & 3) * 2;
#pragma unroll
                for (int h = 0; h < 2; ++h) {
                    int r = r0 + h * 8;
                    float bv = bias[r];
                    float t0 = acc[mt][nt][2 * h] + bv;
                    float t1 = acc[mt][nt][2 * h + 1] + bv;
                    t0 = t0 > 0.f ? t0 : 0.01f * t0;
                    t1 = t1 > 0.f ? t1 : 0.01f * t1;
                    *(float2*)(C + (size_t)r * Nn + cc) = make_float2(t0, t1);
                }
            }
    }
}

// ======================= launch ================================================
extern "C" void kernel_launch(void* const* d_in, const int* in_sizes, int n_in,
                              void* d_out, int out_size) {
    const float* x      = (const float*)d_in[0];
    const float* mixer  = (const float*)d_in[1];
    const float* weight = (const float*)d_in[2];
    const float* wb     = (const float*)d_in[3];
    const float* fw     = (const float*)d_in[4];
    const float* bias   = (const float*)d_in[5];
    const float* S      = (const float*)d_in[6];
    float* out = (float*)d_out;

    cudaFuncSetAttribute(mma_gemm, cudaFuncAttributeMaxDynamicSharedMemorySize, SMEM_GEMM);

    prep_kernel<<<Pc, 256>>>(mixer, weight, wb);
    e_kernel<<<dim3(Nn / 256, NBP), 256>>>(x);
    aij_kernel<<<dim3(Nn, NBP), 256>>>(S);
    aT_kernel<<<dim3(Nn / 32, Nn / 32, NBP), dim3(32, 8)>>>();
    splitx_kernel<<<dim3(Nn / 32, Gc / 32, Bc), dim3(32, 8)>>>(x);
    splitfw_kernel<<<256, 256>>>(fw);

    dim3 g0(Nn / 128, Gc / 128, NBP);   // 8 x 2 x 32
    dim3 g1(Nn / 128, Fc / 128, NBP);
    for (int k = 1; k < Kc; ++k) {
        mma_gemm<<<g0, 256, SMEM_GEMM>>>(bias, out, 0, k);
        ztrans_kernel<<<dim3(Nn / 32, Gc / 32, NBP), dim3(32, 8)>>>(k);
    }
    mma_gemm<<<g1, 256, SMEM_GEMM>>>(bias, out, 1, 0);
}

// round 4
// speedup vs baseline: 2.5374x; 1.2340x over previous
#include <cuda_runtime.h>
#include <cuda_bf16.h>
#include <cstdint>

#define Bc 8
#define Gc 256
#define Nn 1024
#define Pc 4
#define Fc 256
#define Kc 4
#define NBP 32

// ======================= device scratch ======================================
__device__ float g_v1[Pc * Gc];
__device__ float g_v2[Pc * Gc];
__device__ float g_c1[Pc];
__device__ float g_c2[Pc];
__device__ float g_e1[NBP * Nn];
__device__ float g_e2[NBP * Nn];
__device__ __nv_bfloat16 g_ah[(size_t)NBP * Nn * Nn];   // 64 MB aij hi, row-major [j][n]
__device__ __nv_bfloat16 g_al[(size_t)NBP * Nn * Nn];   // 64 MB aij lo
__device__ __nv_bfloat16 g_zsh[(size_t)NBP * Nn * Nn];  // 64 MB z stacked [k*G+g][n] hi
__device__ __nv_bfloat16 g_zsl[(size_t)NBP * Nn * Nn];  // 64 MB lo
__device__ __nv_bfloat16 g_fwh[(size_t)Pc * Fc * Kc * Gc];
__device__ __nv_bfloat16 g_fwl[(size_t)Pc * Fc * Kc * Gc];

__device__ __forceinline__ void split2(float v, __nv_bfloat16& h, __nv_bfloat16& l) {
    h = __float2bfloat16(v);
    l = __float2bfloat16(v - __bfloat162float(h));
}

// ======================= helpers =============================================
__device__ __forceinline__ uint32_t smem_u32(const void* p) {
    uint32_t a;
    asm("{ .reg .u64 t; cvta.to.shared.u64 t, %1; cvt.u32.u64 %0, t; }" : "=r"(a) : "l"(p));
    return a;
}
__device__ __forceinline__ void cpa16(uint32_t dst, const void* src) {
    asm volatile("cp.async.cg.shared.global [%0], [%1], 16;" :: "r"(dst), "l"(src));
}
__device__ __forceinline__ void cpa_commit() { asm volatile("cp.async.commit_group;" ::: "memory"); }

#define SWZ(off) ((off) ^ (((off) >> 3) & 0x70))

__device__ __forceinline__ void ldm_x4(uint32_t& r0, uint32_t& r1, uint32_t& r2, uint32_t& r3,
                                       uint32_t addr) {
    asm volatile("ldmatrix.sync.aligned.m8n8.x4.shared.b16 {%0,%1,%2,%3}, [%4];"
                 : "=r"(r0), "=r"(r1), "=r"(r2), "=r"(r3) : "r"(addr));
}
__device__ __forceinline__ void ldm_x4t(uint32_t& r0, uint32_t& r1, uint32_t& r2, uint32_t& r3,
                                        uint32_t addr) {
    asm volatile("ldmatrix.sync.aligned.m8n8.x4.trans.shared.b16 {%0,%1,%2,%3}, [%4];"
                 : "=r"(r0), "=r"(r1), "=r"(r2), "=r"(r3) : "r"(addr));
}
__device__ __forceinline__ void mma16816(float* c, const uint32_t* a, const uint32_t* b) {
    asm volatile(
        "mma.sync.aligned.m16n8k16.row.col.f32.bf16.bf16.f32 "
        "{%0,%1,%2,%3}, {%4,%5,%6,%7}, {%8,%9}, {%0,%1,%2,%3};"
        : "+f"(c[0]), "+f"(c[1]), "+f"(c[2]), "+f"(c[3])
        : "r"(a[0]), "r"(a[1]), "r"(a[2]), "r"(a[3]), "r"(b[0]), "r"(b[1]));
}

// ======================= prep =================================================
__global__ void prep_kernel(const float* __restrict__ mixer,
                            const float* __restrict__ weight,
                            const float* __restrict__ wb) {
    int p = blockIdx.x, g = threadIdx.x;
    float v1 = 0.f, v2 = 0.f;
#pragma unroll 8
    for (int f = 0; f < Fc; ++f) {
        float w = weight[((size_t)(p * Fc + f)) * Gc + g];
        v1 = fmaf(mixer[p * 2 * Fc + f], w, v1);
        v2 = fmaf(mixer[p * 2 * Fc + Fc + f], w, v2);
    }
    g_v1[p * Gc + g] = v1;
    g_v2[p * Gc + g] = v2;
    if (g == 0) {
        float c1 = 0.f, c2 = 0.f;
        for (int f = 0; f < Fc; ++f) {
            c1 = fmaf(mixer[p * 2 * Fc + f], wb[p * Fc + f], c1);
            c2 = fmaf(mixer[p * 2 * Fc + Fc + f], wb[p * Fc + f], c2);
        }
        g_c1[p] = c1;
        g_c2[p] = c2;
    }
}

// ======================= e1/e2 ================================================
__global__ void e_kernel(const float* __restrict__ x) {
    int bp = blockIdx.y;
    int b = bp >> 2, p = bp & 3;
    int n = blockIdx.x * blockDim.x + threadIdx.x;
    __shared__ float s1[Gc], s2[Gc];
    s1[threadIdx.x] = g_v1[p * Gc + threadIdx.x];
    s2[threadIdx.x] = g_v2[p * Gc + threadIdx.x];
    __syncthreads();
    const float* xb = x + (size_t)b * Gc * Nn + n;
    float a1 = 0.f, a2 = 0.f;
#pragma unroll 8
    for (int g = 0; g < Gc; ++g) {
        float xv = xb[(size_t)g * Nn];
        a1 = fmaf(s1[g], xv, a1);
        a2 = fmaf(s2[g], xv, a2);
    }
    g_e1[bp * Nn + n] = a1 + g_c1[p];
    g_e2[bp * Nn + n] = a2 + g_c2[p];
}

// ======================= x -> zs slice 0 (hi/lo, 4 p replicas) ================
__global__ void splitx_kernel(const float* __restrict__ x) {
    int t = blockIdx.x * blockDim.x + threadIdx.x;   // over Bc*Gc*Nn
    int n = t & (Nn - 1);
    int g = (t >> 10) & (Gc - 1);
    int b = t >> 18;
    __nv_bfloat16 h, l;
    split2(x[t], h, l);
#pragma unroll
    for (int p = 0; p < 4; ++p) {
        size_t o = ((size_t)(b * 4 + p) * Nn + g) * Nn + n;  // row = 0*Gc + g
        g_zsh[o] = h;
        g_zsl[o] = l;
    }
}

// ======================= fw -> bf16 hi/lo =====================================
__global__ void splitfw_kernel(const float* __restrict__ fw) {
    int i = blockIdx.x * blockDim.x + threadIdx.x;
    const int total = Pc * Fc * Kc * Gc;
    for (; i < total; i += gridDim.x * blockDim.x) {
        __nv_bfloat16 h, l;
        split2(fw[i], h, l);
        g_fwh[i] = h;
        g_fwl[i] = l;
    }
}

// ======================= reductions ==========================================
__device__ __forceinline__ float blockReduceMax(float v, float* sm) {
#pragma unroll
    for (int o = 16; o; o >>= 1) v = fmaxf(v, __shfl_xor_sync(0xffffffffu, v, o));
    if ((threadIdx.x & 31) == 0) sm[threadIdx.x >> 5] = v;
    __syncthreads();
    if (threadIdx.x < 32) {
        float t = (threadIdx.x < 8) ? sm[threadIdx.x] : -3.0e38f;
#pragma unroll
        for (int o = 4; o; o >>= 1) t = fmaxf(t, __shfl_xor_sync(0xffffffffu, t, o));
        if (threadIdx.x == 0) sm[0] = t;
    }
    __syncthreads();
    float r = sm[0];
    __syncthreads();
    return r;
}
__device__ __forceinline__ float blockReduceSum(float v, float* sm) {
#pragma unroll
    for (int o = 16; o; o >>= 1) v += __shfl_xor_sync(0xffffffffu, v, o);
    if ((threadIdx.x & 31) == 0) sm[threadIdx.x >> 5] = v;
    __syncthreads();
    if (threadIdx.x < 32) {
        float t = (threadIdx.x < 8) ? sm[threadIdx.x] : 0.f;
#pragma unroll
        for (int o = 4; o; o >>= 1) t += __shfl_xor_sync(0xffffffffu, t, o);
        if (threadIdx.x == 0) sm[0] = t;
    }
    __syncthreads();
    float r = sm[0];
    __syncthreads();
    return r;
}

// ======================= softmax rows -> aij hi/lo row-major ==================
__global__ void aij_kernel(const float* __restrict__ S) {
    int i = blockIdx.x, bp = blockIdx.y, b = bp >> 2;
    __shared__ float sm[8];
    float e2i = g_e2[bp * Nn + i];
    const float* e1r = g_e1 + bp * Nn;
    const float* Sr = S + (size_t)b * Nn * Nn + (size_t)i * Nn;
    float lv[4];
    int mk[4];
    float vmax = -3.0e38f;
#pragma unroll
    for (int q = 0; q < 4; ++q) {
        int j = threadIdx.x + q * 256;
        float s = Sr[j];
        int m = (fabsf(s) > 1e-9f);
        float e = e1r[j] + e2i;
        float l = e > 0.f ? e : 0.2f * e;
        lv[q] = l;
        mk[q] = m;
        if (m) vmax = fmaxf(vmax, l);
    }
    vmax = blockReduceMax(vmax, sm);
    float pv[4];
    float sum = 0.f;
#pragma unroll
    for (int q = 0; q < 4; ++q) {
        float pe = mk[q] ? __expf(lv[q] - vmax) : 0.f;
        pv[q] = pe;
        sum += pe;
    }
    sum = blockReduceSum(sum, sm);
    float inv = 1.f / sum;
    size_t rowo = (size_t)bp * Nn * Nn + (size_t)i * Nn;
#pragma unroll
    for (int q = 0; q < 4; ++q) {
        int j = threadIdx.x + q * 256;
        __nv_bfloat16 h, l;
        split2(pv[q] * inv, h, l);
        g_ah[rowo + j] = h;
        g_al[rowo + j] = l;
    }
}

// ======================= HMMA GEMM ============================================
// CTA tile 128(m) x 256(n), K=1024, BK=32, double-buffered cp.async.
// A: row-major [m][k] hi/lo -> smem 128 rows x 128B (64B hi | 64B lo), SWZ.
// B: row-major [k][n] hi/lo -> smem 32 rows x 1024B (512B hi | 512B lo),
//    chunk-XOR swizzle, consumed with ldmatrix.x4.trans.
// mode 0: zs[kstep] = zs[kstep-1] @ aij        (A=zs slice, B=aij)
// mode 1: out = lrelu(fw @ Zs + bias, 0.01)    (A=fw, B=zs all slices)
#define TBK 32
#define NCH (Nn / TBK)
#define ASTG 16384
#define BSTG 32768
#define STG (ASTG + BSTG)
#define SMEM_GEMM (2 * STG)

__global__ void __launch_bounds__(256, 1)
mma_gemm(const float* __restrict__ bias, float* __restrict__ out, int mode, int kstep) {
    extern __shared__ __align__(1024) char smem[];
    uint32_t sb = smem_u32(smem);
    const int bp = blockIdx.z, p = bp & 3;
    const int m0 = blockIdx.y * 128, n0 = blockIdx.x * 256;
    const int tid = threadIdx.x, wid = tid >> 5, lane = tid & 31;
    const int warp_m = wid >> 2, warp_n = wid & 3;  // 2 x 4 warps, warp tile 64x64
    const size_t NN = (size_t)Nn * Nn;

    const __nv_bfloat16 *Ah, *Al, *Bh, *Bl;
    if (mode == 0) {
        Ah = g_zsh + ((size_t)bp * Nn + (size_t)(kstep - 1) * Gc) * Nn;
        Al = g_zsl + ((size_t)bp * Nn + (size_t)(kstep - 1) * Gc) * Nn;
        Bh = g_ah + (size_t)bp * NN;
        Bl = g_al + (size_t)bp * NN;
    } else {
        Ah = g_fwh + (size_t)p * Fc * Nn;
        Al = g_fwl + (size_t)p * Fc * Nn;
        Bh = g_zsh + (size_t)bp * NN;
        Bl = g_zsl + (size_t)bp * NN;
    }

    float acc[4][8][4];
#pragma unroll
    for (int i = 0; i < 4; ++i)
#pragma unroll
        for (int j = 0; j < 8; ++j)
#pragma unroll
            for (int q = 0; q < 4; ++q) acc[i][j][q] = 0.f;

    auto load_stage = [&](int c, int s) {
        uint32_t base = sb + s * STG;
        int k0 = c * TBK;
        // A: 128 rows x 8 chunks = 1024 ops -> 4/thread
#pragma unroll
        for (int i = 0; i < 4; ++i) {
            int idx = i * 256 + tid;
            int r = idx >> 3, ch = idx & 7;  // ch<4 hi
            const __nv_bfloat16* src = ((ch < 4) ? Ah : Al) + (size_t)(m0 + r) * Nn + k0 + (ch & 3) * 8;
            cpa16(base + SWZ(r * 128 + ch * 16), src);
        }
        // B: 32 rows x 64 chunks = 2048 ops -> 8/thread
#pragma unroll
        for (int i = 0; i < 8; ++i) {
            int idx = i * 256 + tid;
            int r = idx >> 6, c = idx & 63;
            int half = c >> 5, c5 = c & 31;
            const __nv_bfloat16* src = (half ? Bl : Bh) + (size_t)(k0 + r) * Nn + n0 + c5 * 8;
            cpa16(base + ASTG + r * 1024 + half * 512 + ((c5 ^ (r & 7)) * 16), src);
        }
        cpa_commit();
    };

    // lane decomposition for fragment loads
    const int a_row = (lane & 7) + ((lane >> 3) & 1) * 8;  // 0..15
    const int a_k16 = lane >> 4;                           // 0/1
    const int b_krow = lane & 15;
    const int b_nsel = lane >> 4;

    load_stage(0, 0);
    for (int c = 0; c < NCH; ++c) {
        if (c + 1 < NCH) {
            load_stage(c + 1, (c + 1) & 1);
            asm volatile("cp.async.wait_group 1;" ::: "memory");
        } else {
            asm volatile("cp.async.wait_group 0;" ::: "memory");
        }
        __syncthreads();
        uint32_t Abase = sb + (c & 1) * STG;
        uint32_t Bbase = Abase + ASTG;
#pragma unroll
        for (int s = 0; s < 2; ++s) {
            uint32_t ah[4][4], al[4][4];
#pragma unroll
            for (int mt = 0; mt < 4; ++mt) {
                int row = warp_m * 64 + mt * 16 + a_row;
                int chh = s * 2 + a_k16;
                ldm_x4(ah[mt][0], ah[mt][1], ah[mt][2], ah[mt][3],
                       Abase + SWZ(row * 128 + chh * 16));
                ldm_x4(al[mt][0], al[mt][1], al[mt][2], al[mt][3],
                       Abase + SWZ(row * 128 + 64 + chh * 16));
            }
#pragma unroll
            for (int ng = 0; ng < 4; ++ng) {
                int k = s * 16 + b_krow;
                int c5 = (warp_n * 64 + ng * 16) / 8 + b_nsel;  // 16B chunk index
                uint32_t addr = Bbase + k * 1024 + ((c5 ^ (k & 7)) * 16);
                uint32_t bh[4], bl[4];
                ldm_x4t(bh[0], bh[1], bh[2], bh[3], addr);
                ldm_x4t(bl[0], bl[1], bl[2], bl[3], addr + 512);
#pragma unroll
                for (int mt = 0; mt < 4; ++mt) {
                    mma16816(acc[mt][2 * ng], ah[mt], &bh[0]);
                    mma16816(acc[mt][2 * ng], ah[mt], &bl[0]);
                    mma16816(acc[mt][2 * ng], al[mt], &bh[0]);
                    mma16816(acc[mt][2 * ng + 1], ah[mt], &bh[2]);
                    mma16816(acc[mt][2 * ng + 1], ah[mt], &bl[2]);
                    mma16816(acc[mt][2 * ng + 1], al[mt], &bh[2]);
                }
            }
        }
        __syncthreads();
    }

    // ---------------- epilogue ----------------
    const int r_base = m0 + warp_m * 64 + (lane >> 2);
    const int c_base = n0 + warp_n * 64 + (lane & 3) * 2;
    if (mode == 0) {
        __nv_bfloat16* Zh = g_zsh + ((size_t)bp * Nn + (size_t)kstep * Gc) * Nn;
        __nv_bfloat16* Zl = g_zsl + ((size_t)bp * Nn + (size_t)kstep * Gc) * Nn;
#pragma unroll
        for (int mt = 0; mt < 4; ++mt)
#pragma unroll
            for (int nt = 0; nt < 8; ++nt) {
#pragma unroll
                for (int h = 0; h < 2; ++h) {
                    int r = r_base + mt * 16 + h * 8;
                    int cc = c_base + nt * 8;
                    float v0 = acc[mt][nt][2 * h], v1 = acc[mt][nt][2 * h + 1];
                    __nv_bfloat16 h0, l0, h1, l1;
                    split2(v0, h0, l0);
                    split2(v1, h1, l1);
                    __nv_bfloat162 ph, pl;
                    ph.x = h0; ph.y = h1;
                    pl.x = l0; pl.y = l1;
                    *(__nv_bfloat162*)(Zh + (size_t)r * Nn + cc) = ph;
                    *(__nv_bfloat162*)(Zl + (size_t)r * Nn + cc) = pl;
                }
            }
    } else {
        float* C = out + (size_t)bp * Fc * Nn;
#pragma unroll
        for (int mt = 0; mt < 4; ++mt)
#pragma unroll
            for (int nt = 0; nt < 8; ++nt) {
#pragma unroll
                for (int h = 0; h < 2; ++h) {
                    int r = r_base + mt * 16 + h * 8;
                    int cc = c_base + nt * 8;
                    float bv = bias[r];
                    float t0 = acc[mt][nt][2 * h] + bv;
                    float t1 = acc[mt][nt][2 * h + 1] + bv;
                    t0 = t0 > 0.f ? t0 : 0.01f * t0;
                    t1 = t1 > 0.f ? t1 : 0.01f * t1;
                    *(float2*)(C + (size_t)r * Nn + cc) = make_float2(t0, t1);
                }
            }
    }
}

// ======================= launch ================================================
extern "C" void kernel_launch(void* const* d_in, const int* in_sizes, int n_in,
                              void* d_out, int out_size) {
    const float* x      = (const float*)d_in[0];
    const float* mixer  = (const float*)d_in[1];
    const float* weight = (const float*)d_in[2];
    const float* wb     = (const float*)d_in[3];
    const float* fw     = (const float*)d_in[4];
    const float* bias   = (const float*)d_in[5];
    const float* S      = (const float*)d_in[6];
    float* out = (float*)d_out;

    cudaFuncSetAttribute(mma_gemm, cudaFuncAttributeMaxDynamicSharedMemorySize, SMEM_GEMM);

    prep_kernel<<<Pc, 256>>>(mixer, weight, wb);          // 1
    e_kernel<<<dim3(Nn / 256, NBP), 256>>>(x);            // 2
    splitx_kernel<<<(Bc * Gc * Nn) / 256, 256>>>(x);      // 3
    splitfw_kernel<<<256, 256>>>(fw);                     // 4
    aij_kernel<<<dim3(Nn, NBP), 256>>>(S);                // 5

    dim3 gg(Nn / 256, 2, NBP);   // 4 x 2 x 32 = 256 CTAs
    for (int k = 1; k < Kc; ++k)                          // 6,7,8  (ncu captures #6)
        mma_gemm<<<gg, 256, SMEM_GEMM>>>(bias, out, 0, k);
    mma_gemm<<<gg, 256, SMEM_GEMM>>>(bias, out, 1, 0);    // 9
}

// round 5
// speedup vs baseline: 2.5916x; 1.0213x over previous
#include <cuda_runtime.h>
#include <cuda_bf16.h>
#include <cstdint>

#define Bc 8
#define Gc 256
#define Nn 1024
#define Pc 4
#define Fc 256
#define Kc 4
#define NBP 32

// ======================= device scratch ======================================
__device__ float g_e1[NBP * Nn];
__device__ float g_e2[NBP * Nn];
__device__ __nv_bfloat16 g_ah[(size_t)NBP * Nn * Nn];   // aij hi, row-major [j][n]
__device__ __nv_bfloat16 g_al[(size_t)NBP * Nn * Nn];   // aij lo
__device__ __nv_bfloat16 g_zsh[(size_t)NBP * Nn * Nn];  // z stacked [k*G+g][n] hi
__device__ __nv_bfloat16 g_zsl[(size_t)NBP * Nn * Nn];  // lo
__device__ __nv_bfloat16 g_fwh[(size_t)Pc * Fc * Kc * Gc];
__device__ __nv_bfloat16 g_fwl[(size_t)Pc * Fc * Kc * Gc];

__device__ __forceinline__ void split2(float v, __nv_bfloat16& h, __nv_bfloat16& l) {
    h = __float2bfloat16(v);
    l = __float2bfloat16(v - __bfloat162float(h));
}

// ======================= helpers =============================================
__device__ __forceinline__ uint32_t smem_u32(const void* p) {
    uint32_t a;
    asm("{ .reg .u64 t; cvta.to.shared.u64 t, %1; cvt.u32.u64 %0, t; }" : "=r"(a) : "l"(p));
    return a;
}
__device__ __forceinline__ void cpa16(uint32_t dst, const void* src) {
    asm volatile("cp.async.cg.shared.global [%0], [%1], 16;" :: "r"(dst), "l"(src));
}
__device__ __forceinline__ void cpa_commit() { asm volatile("cp.async.commit_group;" ::: "memory"); }

#define SWZ(off) ((off) ^ (((off) >> 3) & 0x70))

__device__ __forceinline__ void ldm_x4(uint32_t& r0, uint32_t& r1, uint32_t& r2, uint32_t& r3,
                                       uint32_t addr) {
    asm volatile("ldmatrix.sync.aligned.m8n8.x4.shared.b16 {%0,%1,%2,%3}, [%4];"
                 : "=r"(r0), "=r"(r1), "=r"(r2), "=r"(r3) : "r"(addr));
}
__device__ __forceinline__ void ldm_x4t(uint32_t& r0, uint32_t& r1, uint32_t& r2, uint32_t& r3,
                                        uint32_t addr) {
    asm volatile("ldmatrix.sync.aligned.m8n8.x4.trans.shared.b16 {%0,%1,%2,%3}, [%4];"
                 : "=r"(r0), "=r"(r1), "=r"(r2), "=r"(r3) : "r"(addr));
}
__device__ __forceinline__ void mma16816(float* c, const uint32_t* a, const uint32_t* b) {
    asm volatile(
        "mma.sync.aligned.m16n8k16.row.col.f32.bf16.bf16.f32 "
        "{%0,%1,%2,%3}, {%4,%5,%6,%7}, {%8,%9}, {%0,%1,%2,%3};"
        : "+f"(c[0]), "+f"(c[1]), "+f"(c[2]), "+f"(c[3])
        : "r"(a[0]), "r"(a[1]), "r"(a[2]), "r"(a[3]), "r"(b[0]), "r"(b[1]));
}

// ======================= fused input split (x -> zs slice0, fw -> hi/lo) ======
__global__ void split_kernel(const float* __restrict__ x, const float* __restrict__ fw) {
    int t = blockIdx.x * blockDim.x + threadIdx.x;
    const int XT = Bc * Gc * Nn;          // 2M
    const int FT = Pc * Fc * Kc * Gc;     // 1M
    if (t < XT) {
        int n = t & (Nn - 1);
        int g = (t >> 10) & (Gc - 1);
        int b = t >> 18;
        __nv_bfloat16 h, l;
        split2(x[t], h, l);
#pragma unroll
        for (int p = 0; p < 4; ++p) {
            size_t o = ((size_t)(b * 4 + p) * Nn + g) * Nn + n;
            g_zsh[o] = h;
            g_zsl[o] = l;
        }
    } else {
        int i = t - XT;
        if (i < FT) {
            __nv_bfloat16 h, l;
            split2(fw[i], h, l);
            g_fwh[i] = h;
            g_fwl[i] = l;
        }
    }
}

// ======================= fused prep + e: e1/e2[bp][n] =========================
__global__ void pe_kernel(const float* __restrict__ x,
                          const float* __restrict__ mixer,
                          const float* __restrict__ weight,
                          const float* __restrict__ wb) {
    int bp = blockIdx.y;
    int b = bp >> 2, p = bp & 3;
    int tid = threadIdx.x;
    __shared__ float s1[Gc], s2[Gc], sc[2];
    // compute v1/v2 for this p (redundant across blocks, trivial cost)
    {
        int g = tid;
        float v1 = 0.f, v2 = 0.f;
        const float* mw1 = mixer + p * 2 * Fc;
        const float* mw2 = mw1 + Fc;
#pragma unroll 8
        for (int f = 0; f < Fc; ++f) {
            float w = weight[((size_t)(p * Fc + f)) * Gc + g];
            v1 = fmaf(mw1[f], w, v1);
            v2 = fmaf(mw2[f], w, v2);
        }
        s1[g] = v1;
        s2[g] = v2;
        if (g == 0) {
            float c1 = 0.f, c2 = 0.f;
            for (int f = 0; f < Fc; ++f) {
                c1 = fmaf(mw1[f], wb[p * Fc + f], c1);
                c2 = fmaf(mw2[f], wb[p * Fc + f], c2);
            }
            sc[0] = c1;
            sc[1] = c2;
        }
    }
    __syncthreads();
    int n = blockIdx.x * blockDim.x + tid;
    const float* xb = x + (size_t)b * Gc * Nn + n;
    float a1 = 0.f, a2 = 0.f;
#pragma unroll 8
    for (int g = 0; g < Gc; ++g) {
        float xv = xb[(size_t)g * Nn];
        a1 = fmaf(s1[g], xv, a1);
        a2 = fmaf(s2[g], xv, a2);
    }
    g_e1[bp * Nn + n] = a1 + sc[0];
    g_e2[bp * Nn + n] = a2 + sc[1];
}

// ======================= reductions ==========================================
__device__ __forceinline__ float blockReduceMax(float v, float* sm) {
#pragma unroll
    for (int o = 16; o; o >>= 1) v = fmaxf(v, __shfl_xor_sync(0xffffffffu, v, o));
    if ((threadIdx.x & 31) == 0) sm[threadIdx.x >> 5] = v;
    __syncthreads();
    if (threadIdx.x < 32) {
        float t = (threadIdx.x < 8) ? sm[threadIdx.x] : -3.0e38f;
#pragma unroll
        for (int o = 4; o; o >>= 1) t = fmaxf(t, __shfl_xor_sync(0xffffffffu, t, o));
        if (threadIdx.x == 0) sm[0] = t;
    }
    __syncthreads();
    float r = sm[0];
    __syncthreads();
    return r;
}
__device__ __forceinline__ float blockReduceSum(float v, float* sm) {
#pragma unroll
    for (int o = 16; o; o >>= 1) v += __shfl_xor_sync(0xffffffffu, v, o);
    if ((threadIdx.x & 31) == 0) sm[threadIdx.x >> 5] = v;
    __syncthreads();
    if (threadIdx.x < 32) {
        float t = (threadIdx.x < 8) ? sm[threadIdx.x] : 0.f;
#pragma unroll
        for (int o = 4; o; o >>= 1) t += __shfl_xor_sync(0xffffffffu, t, o);
        if (threadIdx.x == 0) sm[0] = t;
    }
    __syncthreads();
    float r = sm[0];
    __syncthreads();
    return r;
}

// ======================= softmax rows -> aij hi/lo row-major ==================
__global__ void aij_kernel(const float* __restrict__ S) {
    int i = blockIdx.x, bp = blockIdx.y, b = bp >> 2;
    __shared__ float sm[8];
    float e2i = g_e2[bp * Nn + i];
    const float* e1r = g_e1 + bp * Nn;
    const float* Sr = S + (size_t)b * Nn * Nn + (size_t)i * Nn;
    float lv[4];
    int mk[4];
    float vmax = -3.0e38f;
#pragma unroll
    for (int q = 0; q < 4; ++q) {
        int j = threadIdx.x + q * 256;
        float s = Sr[j];
        int m = (fabsf(s) > 1e-9f);
        float e = e1r[j] + e2i;
        float l = e > 0.f ? e : 0.2f * e;
        lv[q] = l;
        mk[q] = m;
        if (m) vmax = fmaxf(vmax, l);
    }
    vmax = blockReduceMax(vmax, sm);
    float pv[4];
    float sum = 0.f;
#pragma unroll
    for (int q = 0; q < 4; ++q) {
        float pe = mk[q] ? __expf(lv[q] - vmax) : 0.f;
        pv[q] = pe;
        sum += pe;
    }
    sum = blockReduceSum(sum, sm);
    float inv = 1.f / sum;
    size_t rowo = (size_t)bp * Nn * Nn + (size_t)i * Nn;
#pragma unroll
    for (int q = 0; q < 4; ++q) {
        int j = threadIdx.x + q * 256;
        __nv_bfloat16 h, l;
        split2(pv[q] * inv, h, l);
        g_ah[rowo + j] = h;
        g_al[rowo + j] = l;
    }
}

// ======================= HMMA GEMM ============================================
// CTA tile 128(m) x 256(n), K=1024, BK=32, 3-stage cp.async pipeline.
#define TBK 32
#define NCH (Nn / TBK)
#define ASTG 16384
#define BSTG 32768
#define STG (ASTG + BSTG)
#define NSTAGE 3
#define SMEM_GEMM (NSTAGE * STG)

__device__ __forceinline__ void cpa_wait2() { asm volatile("cp.async.wait_group 2;" ::: "memory"); }
__device__ __forceinline__ void cpa_wait1() { asm volatile("cp.async.wait_group 1;" ::: "memory"); }
__device__ __forceinline__ void cpa_wait0() { asm volatile("cp.async.wait_group 0;" ::: "memory"); }

__global__ void __launch_bounds__(256, 1)
mma_gemm(const float* __restrict__ bias, float* __restrict__ out, int mode, int kstep) {
    extern __shared__ __align__(1024) char smem[];
    uint32_t sb = smem_u32(smem);
    const int bp = blockIdx.z, p = bp & 3;
    const int m0 = blockIdx.y * 128, n0 = blockIdx.x * 256;
    const int tid = threadIdx.x, wid = tid >> 5, lane = tid & 31;
    const int warp_m = wid >> 2, warp_n = wid & 3;  // 2 x 4 warps, warp tile 64x64
    const size_t NN = (size_t)Nn * Nn;

    const __nv_bfloat16 *Ah, *Al, *Bh, *Bl;
    if (mode == 0) {
        Ah = g_zsh + ((size_t)bp * Nn + (size_t)(kstep - 1) * Gc) * Nn;
        Al = g_zsl + ((size_t)bp * Nn + (size_t)(kstep - 1) * Gc) * Nn;
        Bh = g_ah + (size_t)bp * NN;
        Bl = g_al + (size_t)bp * NN;
    } else {
        Ah = g_fwh + (size_t)p * Fc * Nn;
        Al = g_fwl + (size_t)p * Fc * Nn;
        Bh = g_zsh + (size_t)bp * NN;
        Bl = g_zsl + (size_t)bp * NN;
    }

    float acc[4][8][4];
#pragma unroll
    for (int i = 0; i < 4; ++i)
#pragma unroll
        for (int j = 0; j < 8; ++j)
#pragma unroll
            for (int q = 0; q < 4; ++q) acc[i][j][q] = 0.f;

    auto load_stage = [&](int c, int s) {
        uint32_t base = sb + s * STG;
        int k0 = c * TBK;
#pragma unroll
        for (int i = 0; i < 4; ++i) {
            int idx = i * 256 + tid;
            int r = idx >> 3, ch = idx & 7;
            const __nv_bfloat16* src = ((ch < 4) ? Ah : Al) + (size_t)(m0 + r) * Nn + k0 + (ch & 3) * 8;
            cpa16(base + SWZ(r * 128 + ch * 16), src);
        }
#pragma unroll
        for (int i = 0; i < 8; ++i) {
            int idx = i * 256 + tid;
            int r = idx >> 6, c = idx & 63;
            int half = c >> 5, c5 = c & 31;
            const __nv_bfloat16* src = (half ? Bl : Bh) + (size_t)(k0 + r) * Nn + n0 + c5 * 8;
            cpa16(base + ASTG + r * 1024 + half * 512 + ((c5 ^ (r & 7)) * 16), src);
        }
        cpa_commit();
    };

    const int a_row = (lane & 7) + ((lane >> 3) & 1) * 8;
    const int a_k16 = lane >> 4;
    const int b_krow = lane & 15;
    const int b_nsel = lane >> 4;

    load_stage(0, 0);
    load_stage(1, 1);
    for (int c = 0; c < NCH; ++c) {
        if (c + 2 < NCH) {
            load_stage(c + 2, (c + 2) % NSTAGE);
            cpa_wait2();
        } else if (c + 1 < NCH) {
            cpa_wait1();
        } else {
            cpa_wait0();
        }
        __syncthreads();
        uint32_t Abase = sb + (c % NSTAGE) * STG;
        uint32_t Bbase = Abase + ASTG;
#pragma unroll
        for (int s = 0; s < 2; ++s) {
            uint32_t ah[4][4], al[4][4];
#pragma unroll
            for (int mt = 0; mt < 4; ++mt) {
                int row = warp_m * 64 + mt * 16 + a_row;
                int chh = s * 2 + a_k16;
                ldm_x4(ah[mt][0], ah[mt][1], ah[mt][2], ah[mt][3],
                       Abase + SWZ(row * 128 + chh * 16));
                ldm_x4(al[mt][0], al[mt][1], al[mt][2], al[mt][3],
                       Abase + SWZ(row * 128 + 64 + chh * 16));
            }
#pragma unroll
            for (int ng = 0; ng < 4; ++ng) {
                int k = s * 16 + b_krow;
                int c5 = (warp_n * 64 + ng * 16) / 8 + b_nsel;
                uint32_t addr = Bbase + k * 1024 + ((c5 ^ (k & 7)) * 16);
                uint32_t bh[4], bl[4];
                ldm_x4t(bh[0], bh[1], bh[2], bh[3], addr);
                ldm_x4t(bl[0], bl[1], bl[2], bl[3], addr + 512);
#pragma unroll
                for (int mt = 0; mt < 4; ++mt) {
                    mma16816(acc[mt][2 * ng], ah[mt], &bh[0]);
                    mma16816(acc[mt][2 * ng], ah[mt], &bl[0]);
                    mma16816(acc[mt][2 * ng], al[mt], &bh[0]);
                    mma16816(acc[mt][2 * ng + 1], ah[mt], &bh[2]);
                    mma16816(acc[mt][2 * ng + 1], ah[mt], &bl[2]);
                    mma16816(acc[mt][2 * ng + 1], al[mt], &bh[2]);
                }
            }
        }
        __syncthreads();
    }

    // ---------------- epilogue ----------------
    const int r_base = m0 + warp_m * 64 + (lane >> 2);
    const int c_base = n0 + warp_n * 64 + (lane & 3) * 2;
    if (mode == 0) {
        __nv_bfloat16* Zh = g_zsh + ((size_t)bp * Nn + (size_t)kstep * Gc) * Nn;
        __nv_bfloat16* Zl = g_zsl + ((size_t)bp * Nn + (size_t)kstep * Gc) * Nn;
#pragma unroll
        for (int mt = 0; mt < 4; ++mt)
#pragma unroll
            for (int nt = 0; nt < 8; ++nt) {
#pragma unroll
                for (int h = 0; h < 2; ++h) {
                    int r = r_base + mt * 16 + h * 8;
                    int cc = c_base + nt * 8;
                    float v0 = acc[mt][nt][2 * h], v1 = acc[mt][nt][2 * h + 1];
                    __nv_bfloat16 h0, l0, h1, l1;
                    split2(v0, h0, l0);
                    split2(v1, h1, l1);
                    __nv_bfloat162 ph, pl;
                    ph.x = h0; ph.y = h1;
                    pl.x = l0; pl.y = l1;
                    *(__nv_bfloat162*)(Zh + (size_t)r * Nn + cc) = ph;
                    *(__nv_bfloat162*)(Zl + (size_t)r * Nn + cc) = pl;
                }
            }
    } else {
        float* C = out + (size_t)bp * Fc * Nn;
#pragma unroll
        for (int mt = 0; mt < 4; ++mt)
#pragma unroll
            for (int nt = 0; nt < 8; ++nt) {
#pragma unroll
                for (int h = 0; h < 2; ++h) {
                    int r = r_base + mt * 16 + h * 8;
                    int cc = c_base + nt * 8;
                    float bv = bias[r];
                    float t0 = acc[mt][nt][2 * h] + bv;
                    float t1 = acc[mt][nt][2 * h + 1] + bv;
                    t0 = t0 > 0.f ? t0 : 0.01f * t0;
                    t1 = t1 > 0.f ? t1 : 0.01f * t1;
                    *(float2*)(C + (size_t)r * Nn + cc) = make_float2(t0, t1);
                }
            }
    }
}

// ======================= launch ================================================
extern "C" void kernel_launch(void* const* d_in, const int* in_sizes, int n_in,
                              void* d_out, int out_size) {
    const float* x      = (const float*)d_in[0];
    const float* mixer  = (const float*)d_in[1];
    const float* weight = (const float*)d_in[2];
    const float* wb     = (const float*)d_in[3];
    const float* fw     = (const float*)d_in[4];
    const float* bias   = (const float*)d_in[5];
    const float* S      = (const float*)d_in[6];
    float* out = (float*)d_out;

    cudaFuncSetAttribute(mma_gemm, cudaFuncAttributeMaxDynamicSharedMemorySize, SMEM_GEMM);

    const int XT = Bc * Gc * Nn, FT = Pc * Fc * Kc * Gc;
    split_kernel<<<(XT + FT + 255) / 256, 256>>>(x, fw);        // 1
    pe_kernel<<<dim3(Nn / 256, NBP), 256>>>(x, mixer, weight, wb);  // 2
    aij_kernel<<<dim3(Nn, NBP), 256>>>(S);                      // 3

    dim3 gg(Nn / 256, 2, NBP);
    for (int k = 1; k < Kc; ++k)                                // 4,5,6  (#4 = GEMM profile)
        mma_gemm<<<gg, 256, SMEM_GEMM>>>(bias, out, 0, k);
    mma_gemm<<<gg, 256, SMEM_GEMM>>>(bias, out, 1, 0);          // 7
}